// round 3
// baseline (speedup 1.0000x reference)
#include <cuda_runtime.h>

#define BB 8
#define CC 256
#define EE 128
#define NN 3136          // 56*56
#define NV (NN/4)        // 784
#define NCH 196          // n-chunk per K1 block
#define NBLK 16          // NN / NCH

__device__ float g_tp[BB * NBLK * CC];   // partial t
__device__ float g_sbp[BB * NBLK];       // partial sbar
__device__ float g_d[BB * CC];

// K1: fused fold + s (shared-only) + partial t + partial sbar.
// grid (NBLK, BB), 256 threads.
__global__ void k1_fused(const float* __restrict__ x,
                         const float* __restrict__ Wq, const float* __restrict__ bq,
                         const float* __restrict__ Wk, const float* __restrict__ bk,
                         const float* __restrict__ Wcat) {
    __shared__ float sa[CC];
    __shared__ float ss[NCH];
    int tid = threadIdx.x;
    int blk = blockIdx.x;
    int b   = blockIdx.y;
    int n0  = blk * NCH;

    // phase 0: a[c=tid] (coalesced Wq/Wk columns) and c0 (redundant per thread)
    float acc = 0.f, c0 = 0.f;
    #pragma unroll 8
    for (int e = 0; e < EE; e++) {
        float wqc = Wcat[e], wkc = Wcat[EE + e];
        acc = fmaf(wqc, Wq[e * CC + tid], fmaf(wkc, Wk[e * CC + tid], acc));
        c0  = fmaf(wqc, bq[e], fmaf(wkc, bk[e], c0));
    }
    sa[tid] = acc;
    __syncthreads();

    // phase 1: s[n] for this chunk, kept in shared only
    const float* xb = x + (size_t)b * CC * NN;
    if (tid < NCH) {
        int n = n0 + tid;
        float y = c0;
        #pragma unroll 8
        for (int c = 0; c < CC; c++)
            y = fmaf(sa[c], xb[(size_t)c * NN + n], y);
        ss[tid] = fmaxf(y, 0.f);
    }
    __syncthreads();

    // phase 2: partial t[c=tid] over this n-chunk (x-slice hot in L1/L2)
    {
        const float4* xr = (const float4*)(xb + (size_t)tid * NN + n0);
        float tacc = 0.f;
        #pragma unroll 7
        for (int i = 0; i < NCH / 4; i++) {
            float4 xv = xr[i];
            tacc += xv.x * ss[4*i] + xv.y * ss[4*i+1] + xv.z * ss[4*i+2] + xv.w * ss[4*i+3];
        }
        g_tp[(b * NBLK + blk) * CC + tid] = tacc;
    }
    // sbar partial (warp 0)
    if (tid < 32) {
        float sb = 0.f;
        for (int i = tid; i < NCH; i += 32) sb += ss[i];
        #pragma unroll
        for (int o = 16; o > 0; o >>= 1) sb += __shfl_down_sync(0xFFFFFFFFu, sb, o);
        if (tid == 0) g_sbp[b * NBLK + blk] = sb;
    }
}

// K2: reduce partials -> t, sbar; then m[e] and d[c]. One block per b, 256 threads.
__global__ void k2_fused(const float* __restrict__ Wv, const float* __restrict__ bv,
                         const float* __restrict__ Wexp, const float* __restrict__ bexp) {
    int b = blockIdx.x;
    int tid = threadIdx.x;
    int w = tid >> 5, lane = tid & 31;
    __shared__ float st[CC];
    __shared__ float sm[EE];
    __shared__ float sbar_s;

    // t[c]
    float tacc = 0.f;
    #pragma unroll
    for (int k = 0; k < NBLK; k++)
        tacc += g_tp[(b * NBLK + k) * CC + tid];
    st[tid] = tacc * (1.0f / NN);
    if (tid == 0) {
        float sb = 0.f;
        #pragma unroll
        for (int k = 0; k < NBLK; k++) sb += g_sbp[b * NBLK + k];
        sbar_s = sb * (1.0f / NN);
    }
    __syncthreads();

    // m[e]: warp w handles e = w*16 .. w*16+15, coalesced Wv rows
    #pragma unroll 4
    for (int j = 0; j < 16; j++) {
        int e = w * 16 + j;
        const float* wr = Wv + (size_t)e * CC;
        float acc = 0.f;
        #pragma unroll
        for (int k = 0; k < 8; k++)
            acc = fmaf(wr[lane + 32 * k], st[lane + 32 * k], acc);
        #pragma unroll
        for (int o = 16; o > 0; o >>= 1)
            acc += __shfl_down_sync(0xFFFFFFFFu, acc, o);
        if (lane == 0) sm[e] = acc + bv[e] * sbar_s;
    }
    __syncthreads();

    // d[c]: warp w handles c = w*32 .. w*32+31, coalesced Wexp rows
    #pragma unroll 4
    for (int j = 0; j < 32; j++) {
        int c = w * 32 + j;
        const float* wr = Wexp + (size_t)c * EE;
        float acc = 0.f;
        #pragma unroll
        for (int k = 0; k < 4; k++)
            acc = fmaf(wr[lane + 32 * k], sm[lane + 32 * k], acc);
        #pragma unroll
        for (int o = 16; o > 0; o >>= 1)
            acc += __shfl_down_sync(0xFFFFFFFFu, acc, o);
        if (lane == 0) g_d[b * CC + c] = acc + bexp[c];
    }
}

// K3: out[b,c,n] = x[b,c,n] + d[b,c]. float4 vectorized; x L2-resident after K1.
__global__ void k3_out(const float* __restrict__ x, float* __restrict__ out) {
    int i = blockIdx.x * blockDim.x + threadIdx.x;  // float4 index
    const int total = BB * CC * NV;
    if (i >= total) return;
    int row = i / NV;   // b*CC + c
    float dv = g_d[row];
    float4 xv = ((const float4*)x)[i];
    float4 o;
    o.x = xv.x + dv;
    o.y = xv.y + dv;
    o.z = xv.z + dv;
    o.w = xv.w + dv;
    ((float4*)out)[i] = o;
}

extern "C" void kernel_launch(void* const* d_in, const int* in_sizes, int n_in,
                              void* d_out, int out_size) {
    const float* x    = (const float*)d_in[0];
    const float* Wq   = (const float*)d_in[1];
    const float* bq   = (const float*)d_in[2];
    const float* Wk   = (const float*)d_in[3];
    const float* bk   = (const float*)d_in[4];
    const float* Wv   = (const float*)d_in[5];
    const float* bv   = (const float*)d_in[6];
    const float* Wcat = (const float*)d_in[7];
    const float* Wexp = (const float*)d_in[8];
    const float* bexp = (const float*)d_in[9];
    float* out = (float*)d_out;

    k1_fused<<<dim3(NBLK, BB), 256>>>(x, Wq, bq, Wk, bk, Wcat);
    k2_fused<<<BB, 256>>>(Wv, bv, Wexp, bexp);

    int total4 = BB * CC * NV;
    k3_out<<<(total4 + 255) / 256, 256>>>(x, out);
}

// round 5
// speedup vs baseline: 1.2033x; 1.2033x over previous
#include <cuda_runtime.h>

#define BB 8
#define CC 256
#define EE 128
#define NN 3136          // 56*56
#define NV (NN/4)        // 784

__device__ float g_s[BB * NN];
__device__ float g_sbar[BB];
__device__ float g_t[BB * CC];
__device__ float g_d[BB * CC];

// K1a: fused fold + s.  s[b,n] = relu(sum_c a[c]*x[b,c,n] + c0),
//      a[c] = wq_c.Wq[:,c] + wk_c.Wk[:,c] computed in-block (coalesced columns).
__global__ void k1a_s(const float* __restrict__ x,
                      const float* __restrict__ Wq, const float* __restrict__ bq,
                      const float* __restrict__ Wk, const float* __restrict__ bk,
                      const float* __restrict__ Wcat) {
    __shared__ float sa[CC];
    int tid = threadIdx.x;
    // a[tid] and c0 (c0 redundant per thread; bq/bk/Wcat broadcast-hot in L1)
    float acc = 0.f, c0 = 0.f;
    #pragma unroll 8
    for (int e = 0; e < EE; e++) {
        float wqc = Wcat[e], wkc = Wcat[EE + e];
        acc = fmaf(wqc, Wq[e * CC + tid], fmaf(wkc, Wk[e * CC + tid], acc));
        c0  = fmaf(wqc, bq[e], fmaf(wkc, bk[e], c0));
    }
    sa[tid] = acc;
    __syncthreads();

    int b = blockIdx.y;
    int n = blockIdx.x * blockDim.x + tid;
    if (n >= NN) return;
    const float* xb = x + (size_t)b * CC * NN + n;
    float y = c0;
    #pragma unroll 16
    for (int c = 0; c < CC; c++)
        y = fmaf(sa[c], xb[(size_t)c * NN], y);
    g_s[b * NN + n] = fmaxf(y, 0.f);
}

// K1b: t[b,c] = (1/N) sum_n s[b,n]*x[b,c,n]. One block per (b,c), coalesced.
//      c==0 blocks also produce sbar[b].
__global__ void k1b_t(const float* __restrict__ x) {
    int bc = blockIdx.x;         // b*CC + c
    int b = bc >> 8;
    bool do_sbar = ((bc & 255) == 0);
    int tid = threadIdx.x;       // 128 threads
    const float4* x4 = (const float4*)(x + (size_t)bc * NN);
    const float4* s4 = (const float4*)(g_s + (size_t)b * NN);
    float acc = 0.f, sacc = 0.f;
    #pragma unroll 2
    for (int i = tid; i < NV; i += 128) {
        float4 xv = x4[i];
        float4 sv = s4[i];
        acc += xv.x * sv.x + xv.y * sv.y + xv.z * sv.z + xv.w * sv.w;
        if (do_sbar) sacc += sv.x + sv.y + sv.z + sv.w;
    }
    #pragma unroll
    for (int o = 16; o > 0; o >>= 1) {
        acc  += __shfl_down_sync(0xFFFFFFFFu, acc, o);
        sacc += __shfl_down_sync(0xFFFFFFFFu, sacc, o);
    }
    __shared__ float red[4], sred[4];
    if ((tid & 31) == 0) { red[tid >> 5] = acc; sred[tid >> 5] = sacc; }
    __syncthreads();
    if (tid == 0) {
        g_t[bc] = (red[0] + red[1] + red[2] + red[3]) * (1.0f / NN);
        if (do_sbar)
            g_sbar[b] = (sred[0] + sred[1] + sred[2] + sred[3]) * (1.0f / NN);
    }
}

// K2: m[e] then d[c], one block per b, warp-per-output coalesced rows.
__global__ void k2_fused(const float* __restrict__ Wv, const float* __restrict__ bv,
                         const float* __restrict__ Wexp, const float* __restrict__ bexp) {
    int b = blockIdx.x;
    int tid = threadIdx.x;
    int w = tid >> 5, lane = tid & 31;
    __shared__ float st[CC];
    __shared__ float sm[EE];
    st[tid] = g_t[b * CC + tid];
    __syncthreads();
    float sbar = g_sbar[b];

    // m[e]: warp w handles 16 e's, coalesced Wv rows
    #pragma unroll 4
    for (int j = 0; j < 16; j++) {
        int e = w * 16 + j;
        const float* wr = Wv + (size_t)e * CC;
        float acc = 0.f;
        #pragma unroll
        for (int k = 0; k < 8; k++)
            acc = fmaf(wr[lane + 32 * k], st[lane + 32 * k], acc);
        #pragma unroll
        for (int o = 16; o > 0; o >>= 1)
            acc += __shfl_down_sync(0xFFFFFFFFu, acc, o);
        if (lane == 0) sm[e] = acc + bv[e] * sbar;
    }
    __syncthreads();

    // d[c]: warp w handles 32 c's, coalesced Wexp rows
    #pragma unroll 4
    for (int j = 0; j < 32; j++) {
        int c = w * 32 + j;
        const float* wr = Wexp + (size_t)c * EE;
        float acc = 0.f;
        #pragma unroll
        for (int k = 0; k < 4; k++)
            acc = fmaf(wr[lane + 32 * k], sm[lane + 32 * k], acc);
        #pragma unroll
        for (int o = 16; o > 0; o >>= 1)
            acc += __shfl_down_sync(0xFFFFFFFFu, acc, o);
        if (lane == 0) g_d[b * CC + c] = acc + bexp[c];
    }
}

// K3: out[b,c,n] = x[b,c,n] + d[b,c]. float4 vectorized.
__global__ void k3_out(const float* __restrict__ x, float* __restrict__ out) {
    int i = blockIdx.x * blockDim.x + threadIdx.x;
    const int total = BB * CC * NV;
    if (i >= total) return;
    int row = i / NV;   // b*CC + c
    float dv = g_d[row];
    float4 xv = ((const float4*)x)[i];
    float4 o;
    o.x = xv.x + dv;
    o.y = xv.y + dv;
    o.z = xv.z + dv;
    o.w = xv.w + dv;
    ((float4*)out)[i] = o;
}

extern "C" void kernel_launch(void* const* d_in, const int* in_sizes, int n_in,
                              void* d_out, int out_size) {
    const float* x    = (const float*)d_in[0];
    const float* Wq   = (const float*)d_in[1];
    const float* bq   = (const float*)d_in[2];
    const float* Wk   = (const float*)d_in[3];
    const float* bk   = (const float*)d_in[4];
    const float* Wv   = (const float*)d_in[5];
    const float* bv   = (const float*)d_in[6];
    const float* Wcat = (const float*)d_in[7];
    const float* Wexp = (const float*)d_in[8];
    const float* bexp = (const float*)d_in[9];
    float* out = (float*)d_out;

    dim3 g1((NN + 255) / 256, BB);
    k1a_s<<<g1, 256>>>(x, Wq, bq, Wk, bk, Wcat);
    k1b_t<<<BB * CC, 128>>>(x);
    k2_fused<<<BB, 256>>>(Wv, bv, Wexp, bexp);

    int total4 = BB * CC * NV;
    k3_out<<<(total4 + 255) / 256, 256>>>(x, out);
}

// round 6
// speedup vs baseline: 1.4870x; 1.2358x over previous
#include <cuda_runtime.h>

#define BB 8
#define CC 256
#define EE 128
#define NN 3136          // 56*56 = 49*64
#define NV 784           // NN/4
#define GRID 592         // 4 * 148  (all co-resident with __launch_bounds__(256,4))
#define TPB 256
#define NCHK 49          // n-chunks of 64 per batch image
#define P1B (BB * NCHK)  // 392 blocks active in phase 1

__device__ float g_ap[16 * CC];     // fold partials
__device__ float g_c0;
__device__ float g_tp[P1B * CC];    // partial t per (b,chunk)
__device__ float g_sbp[P1B];        // partial sbar
__device__ float g_d[BB * CC];
__device__ unsigned g_ctr;
__device__ volatile unsigned g_gen;

__device__ __forceinline__ void gbar() {
    __threadfence();
    __syncthreads();
    if (threadIdx.x == 0) {
        unsigned old = g_gen;
        if (atomicAdd(&g_ctr, 1u) == GRID - 1u) {
            g_ctr = 0u;
            __threadfence();
            g_gen = old + 1u;
        } else {
            while (g_gen == old) { __nanosleep(64); }
        }
    }
    __syncthreads();
}

__global__ void __launch_bounds__(TPB, 4)
fused_all(const float* __restrict__ x,
          const float* __restrict__ Wq, const float* __restrict__ bq,
          const float* __restrict__ Wk, const float* __restrict__ bk,
          const float* __restrict__ Wcat,
          const float* __restrict__ Wv, const float* __restrict__ bv,
          const float* __restrict__ Wexp, const float* __restrict__ bexp,
          float* __restrict__ out) {
    int tid = threadIdx.x;
    int bid = blockIdx.x;
    __shared__ float sa[CC];   // a[] in P1; st[] in P2
    __shared__ float sp[CC];   // y-partials in P1; sm[] in P2
    __shared__ float ss[32];   // s values for current 32-n half
    __shared__ float s_sbar;

    // ---------------- P0: fold partials + c0 ----------------
    if (bid < 16) {
        float acc = 0.f;
        int e0 = bid * 8;
        #pragma unroll
        for (int k = 0; k < 8; k++) {
            int e = e0 + k;
            acc = fmaf(Wcat[e], Wq[e * CC + tid],
                  fmaf(Wcat[EE + e], Wk[e * CC + tid], acc));
        }
        g_ap[bid * CC + tid] = acc;
    } else if (bid == 16 && tid < 32) {
        float c0 = 0.f;
        #pragma unroll
        for (int e = tid; e < EE; e += 32)
            c0 = fmaf(Wcat[e], bq[e], fmaf(Wcat[EE + e], bk[e], c0));
        #pragma unroll
        for (int o = 16; o > 0; o >>= 1) c0 += __shfl_down_sync(0xFFFFFFFFu, c0, o);
        if (tid == 0) g_c0 = c0;
    }
    gbar();

    // ---------------- P1: s (smem-only) + partial t + partial sbar ----------------
    if (bid < P1B) {
        // build a[] in smem
        float a = 0.f;
        #pragma unroll
        for (int k = 0; k < 16; k++) a += g_ap[k * CC + tid];
        sa[tid] = a;
        float c0v = g_c0;
        __syncthreads();

        int b = bid / NCHK;
        int nchunk = bid - b * NCHK;
        int xx = tid & 31, cg = tid >> 5;
        float tp = 0.f;     // partial t for c = tid
        float sbp = 0.f;    // partial sbar (tid<32)

        #pragma unroll
        for (int h = 0; h < 2; h++) {
            int n0 = nchunk * 64 + h * 32;
            // y = sum over this thread's 32 c's at spatial position n0+xx
            const float* xp = x + ((size_t)b * CC + cg * 32) * NN + n0 + xx;
            float y = 0.f;
            #pragma unroll
            for (int k = 0; k < 32; k++)
                y = fmaf(sa[cg * 32 + k], xp[(size_t)k * NN], y);
            sp[tid] = y;
            __syncthreads();
            if (tid < 32) {
                float v = c0v;
                #pragma unroll
                for (int g = 0; g < 8; g++) v += sp[g * 32 + tid];
                v = fmaxf(v, 0.f);
                ss[tid] = v;
                sbp += v;
            }
            __syncthreads();
            // partial t for c = tid over these 32 n (x-slice L1-hot)
            const float4* xr = (const float4*)(x + ((size_t)b * CC + tid) * NN + n0);
            #pragma unroll
            for (int j = 0; j < 8; j++) {
                float4 xv = xr[j];
                tp += xv.x * ss[4*j] + xv.y * ss[4*j+1] + xv.z * ss[4*j+2] + xv.w * ss[4*j+3];
            }
            __syncthreads();
        }
        g_tp[bid * CC + tid] = tp;
        if (tid < 32) {
            #pragma unroll
            for (int o = 16; o > 0; o >>= 1) sbp += __shfl_down_sync(0xFFFFFFFFu, sbp, o);
            if (tid == 0) g_sbp[bid] = sbp;
        }
    }
    gbar();

    // ---------------- P2: reduce t,sbar; m; d  (blocks 0..7) ----------------
    if (bid < BB) {
        int b = bid;
        float tv = 0.f;
        #pragma unroll
        for (int k = 0; k < NCHK; k++)
            tv += g_tp[(b * NCHK + k) * CC + tid];
        sa[tid] = tv * (1.0f / NN);       // sa = st
        if (tid < 32) {
            float sb = 0.f;
            for (int k = tid; k < NCHK; k += 32) sb += g_sbp[b * NCHK + k];
            #pragma unroll
            for (int o = 16; o > 0; o >>= 1) sb += __shfl_down_sync(0xFFFFFFFFu, sb, o);
            if (tid == 0) s_sbar = sb * (1.0f / NN);
        }
        __syncthreads();
        float sbar = s_sbar;
        int w = tid >> 5, lane = tid & 31;

        // m[e] -> sp[e]: warp w handles 16 e's, coalesced Wv rows
        #pragma unroll 4
        for (int j = 0; j < 16; j++) {
            int e = w * 16 + j;
            const float* wr = Wv + (size_t)e * CC;
            float acc = 0.f;
            #pragma unroll
            for (int k = 0; k < 8; k++)
                acc = fmaf(wr[lane + 32 * k], sa[lane + 32 * k], acc);
            #pragma unroll
            for (int o = 16; o > 0; o >>= 1)
                acc += __shfl_down_sync(0xFFFFFFFFu, acc, o);
            if (lane == 0) sp[e] = acc + bv[e] * sbar;
        }
        __syncthreads();

        // d[c]: warp w handles 32 c's, coalesced Wexp rows
        #pragma unroll 4
        for (int j = 0; j < 32; j++) {
            int c = w * 32 + j;
            const float* wr = Wexp + (size_t)c * EE;
            float acc = 0.f;
            #pragma unroll
            for (int k = 0; k < 4; k++)
                acc = fmaf(wr[lane + 32 * k], sp[lane + 32 * k], acc);
            #pragma unroll
            for (int o = 16; o > 0; o >>= 1)
                acc += __shfl_down_sync(0xFFFFFFFFu, acc, o);
            if (lane == 0) g_d[b * CC + c] = acc + bexp[c];
        }
    }
    gbar();

    // ---------------- P3: out = x + d[b,c], float4 ----------------
    {
        const int total4 = BB * CC * NV;
        const float4* x4 = (const float4*)x;
        float4* o4 = (float4*)out;
        for (int i = bid * TPB + tid; i < total4; i += GRID * TPB) {
            int row = i / NV;
            float dv = g_d[row];
            float4 xv = x4[i];
            float4 o;
            o.x = xv.x + dv; o.y = xv.y + dv; o.z = xv.z + dv; o.w = xv.w + dv;
            o4[i] = o;
        }
    }
}

extern "C" void kernel_launch(void* const* d_in, const int* in_sizes, int n_in,
                              void* d_out, int out_size) {
    const float* x    = (const float*)d_in[0];
    const float* Wq   = (const float*)d_in[1];
    const float* bq   = (const float*)d_in[2];
    const float* Wk   = (const float*)d_in[3];
    const float* bk   = (const float*)d_in[4];
    const float* Wv   = (const float*)d_in[5];
    const float* bv   = (const float*)d_in[6];
    const float* Wcat = (const float*)d_in[7];
    const float* Wexp = (const float*)d_in[8];
    const float* bexp = (const float*)d_in[9];
    float* out = (float*)d_out;

    fused_all<<<GRID, TPB>>>(x, Wq, bq, Wk, bk, Wcat, Wv, bv, Wexp, bexp, out);
}

// round 7
// speedup vs baseline: 1.5701x; 1.0559x over previous
#include <cuda_runtime.h>

#define BB 8
#define CC 256
#define EE 128
#define NN 3136          // 56*56 = 49*64
#define NV 784           // NN/4
#define GRID 592         // 4 * 148, all co-resident with __launch_bounds__(256,4)
#define TPB 256
#define CHUNK 64
#define NCHK 49          // NN / CHUNK
#define P1B (BB * NCHK)  // 392

__device__ float g_ap[16 * CC];     // fold partials
__device__ float g_c0;
__device__ float g_tp[P1B * CC];    // partial t per (b,chunk)
__device__ float g_sbp[P1B];        // partial sbar
__device__ float g_d[BB * CC];
__device__ unsigned g_ctr;
__device__ volatile unsigned g_gen;

__device__ __forceinline__ void gbar() {
    __threadfence();
    __syncthreads();
    if (threadIdx.x == 0) {
        unsigned old = g_gen;
        if (atomicAdd(&g_ctr, 1u) == GRID - 1u) {
            g_ctr = 0u;
            __threadfence();
            g_gen = old + 1u;
        } else {
            while (g_gen == old) { __nanosleep(64); }
        }
    }
    __syncthreads();
}

__global__ void __launch_bounds__(TPB, 4)
fused_all(const float* __restrict__ x,
          const float* __restrict__ Wq, const float* __restrict__ bq,
          const float* __restrict__ Wk, const float* __restrict__ bk,
          const float* __restrict__ Wcat,
          const float* __restrict__ Wv, const float* __restrict__ bv,
          const float* __restrict__ Wexp, const float* __restrict__ bexp,
          float* __restrict__ out) {
    int tid = threadIdx.x;
    int bid = blockIdx.x;
    __shared__ float sa[CC];   // a[] in P1; st[] in P2
    __shared__ float sp[CC];   // y-partials in P1; sm[] in P2
    __shared__ float ss[CHUNK];
    __shared__ float s_sbar;

    // ---------------- P0: fold partials + c0 ----------------
    if (bid < 16) {
        float acc = 0.f;
        int e0 = bid * 8;
        #pragma unroll
        for (int k = 0; k < 8; k++) {
            int e = e0 + k;
            acc = fmaf(Wcat[e], Wq[e * CC + tid],
                  fmaf(Wcat[EE + e], Wk[e * CC + tid], acc));
        }
        g_ap[bid * CC + tid] = acc;
    } else if (bid == 16 && tid < 32) {
        float c0 = 0.f;
        #pragma unroll
        for (int e = tid; e < EE; e += 32)
            c0 = fmaf(Wcat[e], bq[e], fmaf(Wcat[EE + e], bk[e], c0));
        #pragma unroll
        for (int o = 16; o > 0; o >>= 1) c0 += __shfl_down_sync(0xFFFFFFFFu, c0, o);
        if (tid == 0) g_c0 = c0;
    }
    gbar();

    // ---------------- P1: s (smem-only) + partial t + partial sbar ----------------
    if (bid < P1B) {
        // build a[] in smem from fold partials (coalesced, tiny)
        float a = 0.f;
        #pragma unroll
        for (int k = 0; k < 16; k++) a += g_ap[k * CC + tid];
        sa[tid] = a;
        __syncthreads();

        int b = bid / NCHK;
        int nchunk = bid - b * NCHK;
        int n0 = nchunk * CHUNK;
        const float* xb = x + (size_t)b * CC * NN;

        // y-phase: thread (cg = tid>>6, xx = tid&63) sums 64 c's at n = n0+xx
        {
            int xx = tid & 63, cg = tid >> 6;
            const float* xp = xb + (size_t)(cg * 64) * NN + n0 + xx;
            float y = 0.f;
            #pragma unroll 16
            for (int k = 0; k < 64; k++)
                y = fmaf(sa[cg * 64 + k], xp[(size_t)k * NN], y);
            sp[tid] = y;
        }
        __syncthreads();
        if (tid < CHUNK) {
            float v = g_c0 + sp[tid] + sp[64 + tid] + sp[128 + tid] + sp[192 + tid];
            ss[tid] = fmaxf(v, 0.f);
        }
        __syncthreads();

        // sbar partial (warp 0)
        if (tid < 32) {
            float sb = ss[tid] + ss[32 + tid];
            #pragma unroll
            for (int o = 16; o > 0; o >>= 1) sb += __shfl_down_sync(0xFFFFFFFFu, sb, o);
            if (tid == 0) g_sbp[bid] = sb;
        }

        // t-phase: warp w owns c = w*32+j; lanes cover the 64 n as float2 (coalesced)
        {
            int w = tid >> 5, lane = tid & 31;
            float2 sv = ((const float2*)ss)[lane];
            #pragma unroll 4
            for (int j = 0; j < 32; j++) {
                int c = w * 32 + j;
                float2 xv = ((const float2*)(xb + (size_t)c * NN + n0))[lane];
                float val = xv.x * sv.x + xv.y * sv.y;
                #pragma unroll
                for (int o = 16; o > 0; o >>= 1)
                    val += __shfl_down_sync(0xFFFFFFFFu, val, o);
                if (lane == 0) g_tp[bid * CC + c] = val;
            }
        }
    }
    gbar();

    // ---------------- P2: reduce t,sbar; m; d  (blocks 0..7) ----------------
    if (bid < BB) {
        int b = bid;
        float tv = 0.f;
        #pragma unroll
        for (int k = 0; k < NCHK; k++)
            tv += g_tp[(b * NCHK + k) * CC + tid];
        sa[tid] = tv * (1.0f / NN);       // sa = st
        if (tid < 32) {
            float sb = 0.f;
            for (int k = tid; k < NCHK; k += 32) sb += g_sbp[b * NCHK + k];
            #pragma unroll
            for (int o = 16; o > 0; o >>= 1) sb += __shfl_down_sync(0xFFFFFFFFu, sb, o);
            if (tid == 0) s_sbar = sb * (1.0f / NN);
        }
        __syncthreads();
        float sbar = s_sbar;
        int w = tid >> 5, lane = tid & 31;

        // m[e] -> sp[e]
        #pragma unroll 4
        for (int j = 0; j < 16; j++) {
            int e = w * 16 + j;
            const float* wr = Wv + (size_t)e * CC;
            float acc = 0.f;
            #pragma unroll
            for (int k = 0; k < 8; k++)
                acc = fmaf(wr[lane + 32 * k], sa[lane + 32 * k], acc);
            #pragma unroll
            for (int o = 16; o > 0; o >>= 1)
                acc += __shfl_down_sync(0xFFFFFFFFu, acc, o);
            if (lane == 0) sp[e] = acc + bv[e] * sbar;
        }
        __syncthreads();

        // d[c]
        #pragma unroll 4
        for (int j = 0; j < 32; j++) {
            int c = w * 32 + j;
            const float* wr = Wexp + (size_t)c * EE;
            float acc = 0.f;
            #pragma unroll
            for (int k = 0; k < 4; k++)
                acc = fmaf(wr[lane + 32 * k], sp[lane + 32 * k], acc);
            #pragma unroll
            for (int o = 16; o > 0; o >>= 1)
                acc += __shfl_down_sync(0xFFFFFFFFu, acc, o);
            if (lane == 0) g_d[b * CC + c] = acc + bexp[c];
        }
    }
    gbar();

    // ---------------- P3: out = x + d[b,c], float4 ----------------
    {
        const int total4 = BB * CC * NV;
        const float4* x4 = (const float4*)x;
        float4* o4 = (float4*)out;
        for (int i = bid * TPB + tid; i < total4; i += GRID * TPB) {
            int row = i / NV;
            float dv = g_d[row];
            float4 xv = x4[i];
            float4 o;
            o.x = xv.x + dv; o.y = xv.y + dv; o.z = xv.z + dv; o.w = xv.w + dv;
            o4[i] = o;
        }
    }
}

extern "C" void kernel_launch(void* const* d_in, const int* in_sizes, int n_in,
                              void* d_out, int out_size) {
    const float* x    = (const float*)d_in[0];
    const float* Wq   = (const float*)d_in[1];
    const float* bq   = (const float*)d_in[2];
    const float* Wk   = (const float*)d_in[3];
    const float* bk   = (const float*)d_in[4];
    const float* Wv   = (const float*)d_in[5];
    const float* bv   = (const float*)d_in[6];
    const float* Wcat = (const float*)d_in[7];
    const float* Wexp = (const float*)d_in[8];
    const float* bexp = (const float*)d_in[9];
    float* out = (float*)d_out;

    fused_all<<<GRID, TPB>>>(x, Wq, bq, Wk, bk, Wcat, Wv, bv, Wexp, bexp, out);
}

// round 8
// speedup vs baseline: 1.6959x; 1.0801x over previous
#include <cuda_runtime.h>

#define BB 8
#define CC 256
#define EE 128
#define NN 3136          // 56*56 = 49*64
#define NV 784           // NN/4
#define GRID 592         // 4 * 148, all co-resident with __launch_bounds__(256,4)
#define TPB 256
#define CHUNK 64
#define NCHK 49          // NN / CHUNK
#define P1B (BB * NCHK)  // 392

__device__ float g_ap[16 * CC];     // fold partials
__device__ float g_c0;
__device__ float g_tp[P1B * CC];    // partial t per (b,chunk)
__device__ float g_sbp[P1B];        // partial sbar
__device__ float g_d[BB * CC];
__device__ unsigned g_ctr;
__device__ volatile unsigned g_gen;

__device__ __forceinline__ void gbar() {
    __threadfence();
    __syncthreads();
    if (threadIdx.x == 0) {
        unsigned old = g_gen;
        if (atomicAdd(&g_ctr, 1u) == GRID - 1u) {
            g_ctr = 0u;
            __threadfence();
            g_gen = old + 1u;
        } else {
            while (g_gen == old) { __nanosleep(64); }
        }
    }
    __syncthreads();
}

__global__ void __launch_bounds__(TPB, 4)
fused_all(const float* __restrict__ x,
          const float* __restrict__ Wq, const float* __restrict__ bq,
          const float* __restrict__ Wk, const float* __restrict__ bk,
          const float* __restrict__ Wcat,
          const float* __restrict__ Wv, const float* __restrict__ bv,
          const float* __restrict__ Wexp, const float* __restrict__ bexp,
          float* __restrict__ out) {
    int tid = threadIdx.x;
    int bid = blockIdx.x;
    __shared__ float sa[CC];   // a[] in P1; st[] in P2
    __shared__ float sp[CC];   // y-partials in P1; sm[] in P2
    __shared__ float ss[32];   // s for current 32-n half
    __shared__ float s_sbar;

    // ---------------- P0: fold partials + c0 ----------------
    if (bid < 16) {
        float acc = 0.f;
        int e0 = bid * 8;
        #pragma unroll
        for (int k = 0; k < 8; k++) {
            int e = e0 + k;
            acc = fmaf(Wcat[e], Wq[e * CC + tid],
                  fmaf(Wcat[EE + e], Wk[e * CC + tid], acc));
        }
        g_ap[bid * CC + tid] = acc;
    } else if (bid == 16 && tid < 32) {
        float c0 = 0.f;
        #pragma unroll
        for (int e = tid; e < EE; e += 32)
            c0 = fmaf(Wcat[e], bq[e], fmaf(Wcat[EE + e], bk[e], c0));
        #pragma unroll
        for (int o = 16; o > 0; o >>= 1) c0 += __shfl_down_sync(0xFFFFFFFFu, c0, o);
        if (tid == 0) g_c0 = c0;
    }
    gbar();

    // ---------------- P1: s (smem-only) + partial t + partial sbar ----------------
    if (bid < P1B) {
        float a = 0.f;
        #pragma unroll
        for (int k = 0; k < 16; k++) a += g_ap[k * CC + tid];
        sa[tid] = a;
        __syncthreads();

        int b = bid / NCHK;
        int nchunk = bid - b * NCHK;
        int n0 = nchunk * CHUNK;
        int w = tid >> 5, lane = tid & 31;
        const float* xb = x + (size_t)b * CC * NN;

        float tsum = 0.f;   // t accumulator: lane owns c = w*32 + lane
        float sbp = 0.f;    // sbar partial (tid<32)

        #pragma unroll
        for (int h = 0; h < 2; h++) {
            const float* base = xb + (size_t)(w * 32) * NN + n0 + h * 32 + lane;
            // y-phase: lane accumulates its n over this warp's 32 c-rows (coalesced)
            float yacc = 0.f;
            #pragma unroll
            for (int j = 0; j < 32; j++)
                yacc = fmaf(sa[w * 32 + j], base[(size_t)j * NN], yacc);
            sp[tid] = yacc;
            __syncthreads();
            // s for this half
            if (tid < 32) {
                float v = g_c0;
                #pragma unroll
                for (int g = 0; g < 8; g++) v += sp[g * 32 + tid];
                v = fmaxf(v, 0.f);
                ss[tid] = v;
                sbp += v;
            }
            __syncthreads();
            // t-phase: same rows, L1-hot; butterfly gives sum to all lanes,
            // lane j keeps the value for c = w*32 + j
            float sval = ss[lane];
            #pragma unroll
            for (int j = 0; j < 32; j++) {
                float val = base[(size_t)j * NN] * sval;
                #pragma unroll
                for (int o = 16; o > 0; o >>= 1)
                    val += __shfl_xor_sync(0xFFFFFFFFu, val, o);
                if (lane == j) tsum += val;
            }
            __syncthreads();
        }
        g_tp[bid * CC + tid] = tsum;   // coalesced: tid = w*32+lane
        if (tid < 32) {
            #pragma unroll
            for (int o = 16; o > 0; o >>= 1) sbp += __shfl_xor_sync(0xFFFFFFFFu, sbp, o);
            if (tid == 0) g_sbp[bid] = sbp;
        }
    }
    gbar();

    // ---------------- P2: reduce t,sbar; m; d  (blocks 0..7) ----------------
    if (bid < BB) {
        int b = bid;
        float tv = 0.f;
        #pragma unroll
        for (int k = 0; k < NCHK; k++)
            tv += g_tp[(b * NCHK + k) * CC + tid];
        sa[tid] = tv * (1.0f / NN);       // sa = st
        if (tid < 32) {
            float sb = 0.f;
            for (int k = tid; k < NCHK; k += 32) sb += g_sbp[b * NCHK + k];
            #pragma unroll
            for (int o = 16; o > 0; o >>= 1) sb += __shfl_xor_sync(0xFFFFFFFFu, sb, o);
            if (tid == 0) s_sbar = sb * (1.0f / NN);
        }
        __syncthreads();
        float sbar = s_sbar;
        int w = tid >> 5, lane = tid & 31;

        // m[e] -> sp[e]
        #pragma unroll 4
        for (int j = 0; j < 16; j++) {
            int e = w * 16 + j;
            const float* wr = Wv + (size_t)e * CC;
            float acc = 0.f;
            #pragma unroll
            for (int k = 0; k < 8; k++)
                acc = fmaf(wr[lane + 32 * k], sa[lane + 32 * k], acc);
            #pragma unroll
            for (int o = 16; o > 0; o >>= 1)
                acc += __shfl_xor_sync(0xFFFFFFFFu, acc, o);
            if (lane == 0) sp[e] = acc + bv[e] * sbar;
        }
        __syncthreads();

        // d[c]
        #pragma unroll 4
        for (int j = 0; j < 32; j++) {
            int c = w * 32 + j;
            const float* wr = Wexp + (size_t)c * EE;
            float acc = 0.f;
            #pragma unroll
            for (int k = 0; k < 4; k++)
                acc = fmaf(wr[lane + 32 * k], sp[lane + 32 * k], acc);
            #pragma unroll
            for (int o = 16; o > 0; o >>= 1)
                acc += __shfl_xor_sync(0xFFFFFFFFu, acc, o);
            if (lane == 0) g_d[b * CC + c] = acc + bexp[c];
        }
    }
    gbar();

    // ---------------- P3: out = x + d[b,c], float4 ----------------
    {
        const int total4 = BB * CC * NV;
        const float4* x4 = (const float4*)x;
        float4* o4 = (float4*)out;
        for (int i = bid * TPB + tid; i < total4; i += GRID * TPB) {
            int row = i / NV;
            float dv = g_d[row];
            float4 xv = x4[i];
            float4 o;
            o.x = xv.x + dv; o.y = xv.y + dv; o.z = xv.z + dv; o.w = xv.w + dv;
            o4[i] = o;
        }
    }
}

extern "C" void kernel_launch(void* const* d_in, const int* in_sizes, int n_in,
                              void* d_out, int out_size) {
    const float* x    = (const float*)d_in[0];
    const float* Wq   = (const float*)d_in[1];
    const float* bq   = (const float*)d_in[2];
    const float* Wk   = (const float*)d_in[3];
    const float* bk   = (const float*)d_in[4];
    const float* Wv   = (const float*)d_in[5];
    const float* bv   = (const float*)d_in[6];
    const float* Wcat = (const float*)d_in[7];
    const float* Wexp = (const float*)d_in[8];
    const float* bexp = (const float*)d_in[9];
    float* out = (float*)d_out;

    fused_all<<<GRID, TPB>>>(x, Wq, bq, Wk, bk, Wcat, Wv, bv, Wexp, bexp, out);
}